// round 15
// baseline (speedup 1.0000x reference)
#include <cuda_runtime.h>
#include <cuda_bf16.h>
#include <cuda_fp16.h>
#include <math.h>
#include <stdint.h>

// ---------------------------------------------------------------------------
// GCNClassifier: 4x GCNConv(512,512,512,256) + mean-pool + FC(256->64->1)
// R15: R13 hot kernels restored (best: .ca 2-stage GEMM, 2x-unroll half2 agg)
//      + CSR build chain forked onto a second stream (overlaps conv+gemm L1),
//      + dis fused into scanA.
// ---------------------------------------------------------------------------

#define NN 100000
#define NP 100096          // padded to multiple of 128 (GEMM M tiles)
#define EE 1600000
#define FH 512
#define FO 256
#define NB 391             // ceil(NN/256)

// Scratch (device globals — no runtime allocation allowed)
__device__ uint32_t g_act0[NP * 128];   // e4m3 activations (ping)  [row][128 u32]
__device__ uint32_t g_act1[NP * 128];   // e4m3 activations (pong)
__device__ uint32_t g_xwb[NP * 128];    // e4m3 GEMM output
__device__ uint32_t g_wp[229376];       // e4m3 weights TRANSPOSED [N][K/4 u32]
__device__ int      g_cnt[NN];
__device__ int      g_off[NN + 1];
__device__ int      g_cur[NN];
__device__ int      g_bsum[NB];
__device__ int      g_boff[NB];
__device__ int      g_srcA[EE];
__device__ uint32_t g_enA[EE];          // edge norm as half2 broadcast
__device__ float    g_dis[NN];
__device__ float    g_pool[FO];
__device__ int      g_is64;

// Side stream + fork/join events, created once at static-init time.
// No device-memory APIs are called here; streams/events only.
static cudaStream_t g_s1 = 0;
static cudaEvent_t  g_evFork = 0, g_evJoin = 0;
namespace {
struct StreamInit {
    StreamInit() {
        cudaStreamCreateWithFlags(&g_s1, cudaStreamNonBlocking);
        cudaEventCreateWithFlags(&g_evFork, cudaEventDisableTiming);
        cudaEventCreateWithFlags(&g_evJoin, cudaEventDisableTiming);
    }
};
StreamInit g_streamInit;
}

__device__ __forceinline__ float leaky(float x) {
    return x >= 0.0f ? x : 0.01f * x;
}

__device__ __forceinline__ __half2 u32h2(uint32_t u) {
    return *reinterpret_cast<__half2*>(&u);
}
__device__ __forceinline__ uint32_t h2u32(__half2 h) {
    return *reinterpret_cast<uint32_t*>(&h);
}

// fp8 u32 (4 e4m3) -> two half2
__device__ __forceinline__ void unpk_h2(uint32_t w, __half2& h0, __half2& h1) {
    uint32_t fa, fb;
    unsigned short lo = (unsigned short)(w & 0xffff);
    unsigned short hi = (unsigned short)(w >> 16);
    asm("cvt.rn.f16x2.e4m3x2 %0, %1;" : "=r"(fa) : "h"(lo));
    asm("cvt.rn.f16x2.e4m3x2 %0, %1;" : "=r"(fb) : "h"(hi));
    h0 = u32h2(fa);
    h1 = u32h2(fb);
}

// two half2 -> fp8 u32
__device__ __forceinline__ uint32_t pkh2(__half2 h0, __half2 h1) {
    unsigned short lo, hi;
    uint32_t u0 = h2u32(h0), u1 = h2u32(h1);
    asm("cvt.rn.satfinite.e4m3x2.f16x2 %0, %1;" : "=h"(lo) : "r"(u0));
    asm("cvt.rn.satfinite.e4m3x2.f16x2 %0, %1;" : "=h"(hi) : "r"(u1));
    return (uint32_t)lo | ((uint32_t)hi << 16);
}

// leaky in half2: max(x, 0.01*x)
__device__ __forceinline__ __half2 lk2(__half2 x) {
    const __half2 c = __floats2half2_rn(0.01f, 0.01f);
    return __hmax2(x, __hmul2(x, c));
}

// pack 4 floats -> 4 e4m3 in a u32 (byte i = col i)
__device__ __forceinline__ uint32_t pk8(float a, float b, float c, float d) {
    unsigned short lo, hi;
    asm("cvt.rn.satfinite.e4m3x2.f32 %0, %1, %2;" : "=h"(lo) : "f"(b), "f"(a));
    asm("cvt.rn.satfinite.e4m3x2.f32 %0, %1, %2;" : "=h"(hi) : "f"(d), "f"(c));
    return (uint32_t)lo | ((uint32_t)hi << 16);
}

__device__ __forceinline__ int edge_word(const int* __restrict__ w, int p, int is64) {
    return is64 ? w[2 * p] : w[p];   // little-endian: low word == value
}

__device__ __forceinline__ void mma_e4m3(float& c0, float& c1, float& c2, float& c3,
                                         uint32_t a0, uint32_t a1, uint32_t a2, uint32_t a3,
                                         uint32_t b0, uint32_t b1) {
    asm volatile(
        "mma.sync.aligned.m16n8k32.row.col.f32.e4m3.e4m3.f32 "
        "{%0,%1,%2,%3}, {%4,%5,%6,%7}, {%8,%9}, {%0,%1,%2,%3};"
        : "+f"(c0), "+f"(c1), "+f"(c2), "+f"(c3)
        : "r"(a0), "r"(a1), "r"(a2), "r"(a3), "r"(b0), "r"(b1));
}

__device__ __forceinline__ void ldsm_x4(uint32_t& r0, uint32_t& r1,
                                        uint32_t& r2, uint32_t& r3, uint32_t addr) {
    asm volatile("ldmatrix.sync.aligned.m8n8.x4.shared.b16 {%0,%1,%2,%3}, [%4];"
                 : "=r"(r0), "=r"(r1), "=r"(r2), "=r"(r3) : "r"(addr));
}

__device__ __forceinline__ void cp16(uint32_t smem, const void* g) {
    asm volatile("cp.async.ca.shared.global [%0], [%1], 16;" :: "r"(smem), "l"(g));
}

// ---------------------------------------------------------------------------
// dtype detection (parallel): int64 values < N have all-zero odd words
// ---------------------------------------------------------------------------
__global__ void detect_kernel(const int* __restrict__ w) {
    __shared__ int bad;
    if (threadIdx.x == 0) bad = 0;
    __syncthreads();
    int v = w[1 + 2 * threadIdx.x];   // odd words 1..511
    if (v != 0) bad = 1;
    __syncthreads();
    if (threadIdx.x == 0) g_is64 = bad ? 0 : 1;
}

// ---------------------------------------------------------------------------
// CSR build
// ---------------------------------------------------------------------------
__global__ void zero_kernel() {
    int i = blockIdx.x * blockDim.x + threadIdx.x;
    if (i < NN) g_cnt[i] = 0;
    if (i < FO) g_pool[i] = 0.0f;
}

__global__ void count_kernel(const int* __restrict__ w) {
    int e = blockIdx.x * blockDim.x + threadIdx.x;
    if (e < EE) {
        int is64 = g_is64;
        int d = edge_word(w, EE + e, is64);
        atomicAdd(&g_cnt[d], 1);
    }
}

// Parallel scan, 3 phases (scanA also computes dis)
__global__ void scanA_kernel() {   // block partial sums + dis
    __shared__ int sh[256];
    int t = threadIdx.x;
    int i = blockIdx.x * 256 + t;
    int v = (i < NN) ? g_cnt[i] : 0;
    if (i < NN) g_dis[i] = rsqrtf((float)v + 1.0f);
    sh[t] = v;
    __syncthreads();
    for (int off = 128; off > 0; off >>= 1) {
        if (t < off) sh[t] += sh[t + off];
        __syncthreads();
    }
    if (t == 0) g_bsum[blockIdx.x] = sh[0];
}

__global__ __launch_bounds__(512) void scanB_kernel() {  // scan of 391 block sums
    __shared__ int sh[512];
    int t = threadIdx.x;
    int v = (t < NB) ? g_bsum[t] : 0;
    sh[t] = v;
    __syncthreads();
    for (int off = 1; off < 512; off <<= 1) {
        int u = (t >= off) ? sh[t - off] : 0;
        __syncthreads();
        sh[t] += u;
        __syncthreads();
    }
    if (t < NB) g_boff[t] = sh[t] - v;   // exclusive
    if (t == 0) g_off[NN] = EE;
}

__global__ void scanC_kernel() {   // block-local exclusive scan + offsets
    __shared__ int sh[256];
    int b = blockIdx.x, t = threadIdx.x;
    int i = b * 256 + t;
    int v = (i < NN) ? g_cnt[i] : 0;
    sh[t] = v;
    __syncthreads();
    for (int off = 1; off < 256; off <<= 1) {
        int u = (t >= off) ? sh[t - off] : 0;
        __syncthreads();
        sh[t] += u;
        __syncthreads();
    }
    if (i < NN) {
        int excl = g_boff[b] + sh[t] - v;
        g_off[i] = excl;
        g_cur[i] = excl;
    }
}

__global__ void fill_kernel(const int* __restrict__ w) {
    int e = blockIdx.x * blockDim.x + threadIdx.x;
    if (e < EE) {
        int is64 = g_is64;
        int s = edge_word(w, e, is64);
        int d = edge_word(w, EE + e, is64);
        int p = atomicAdd(&g_cur[d], 1);
        g_srcA[p] = s;
        g_enA[p] = h2u32(__float2half2_rn(g_dis[s] * g_dis[d]));
    }
}

// ---------------------------------------------------------------------------
// weight pack TRANSPOSED fp8: W[K][N] f32 -> g_wp[off + n*128 + kk]
// ---------------------------------------------------------------------------
__global__ void convwT_kernel(const float* __restrict__ W, int N, int off) {
    int idx = blockIdx.x * blockDim.x + threadIdx.x;
    int tot = N * 128;
    if (idx < tot) {
        int n = idx >> 7, kk = idx & 127;
        int k0 = kk * 4;
        g_wp[off + idx] = pk8(W[(k0 + 0) * N + n], W[(k0 + 1) * N + n],
                              W[(k0 + 2) * N + n], W[(k0 + 3) * N + n]);
    }
}

// x f32 -> act0 fp8
__global__ void convx_kernel(const float* __restrict__ x) {
    int idx = blockIdx.x * blockDim.x + threadIdx.x;  // < NN*128
    if (idx < NN * 128) {
        float4 v = ((const float4*)x)[idx];
        g_act0[idx] = pk8(v.x, v.y, v.z, v.w);
    }
}

// ---------------------------------------------------------------------------
// fp8 tensor-core GEMM: xwb[M, Ntot] = act[M,512] @ Wt^T   (e4m3, f32 accum)
// BM=128, BN=128 (fp8 cols), BK=64 fp8 (16 u32). 256 thr = 8 warps, wt 32x64.
// 2 CTAs/SM; single __syncthreads per k-iteration; hoisted LDSM addresses.
// (R13-proven configuration: cp.async.ca, 2-stage static smem.)
// ---------------------------------------------------------------------------
#define STAGE_U32 (128 * 20)         // one stage of A or B (10240 B)

__global__ __launch_bounds__(256, 2) void gemm_fp8(int aSel, int wOff, int cStride)
{
    __shared__ __align__(16) union {
        struct { uint32_t A[2][128][20]; uint32_t B[2][128][20]; } s;
        uint16_t e[128][72];   // epilogue stage: 128 rows x 64 u16 (+pad)
    } sm;

    const uint32_t* A = aSel ? g_act1 : g_act0;   // [NP][128 u32]
    const uint32_t* Wt = g_wp + wOff;             // [Ntot][128 u32]
    int tid = threadIdx.x;
    int lane = tid & 31, warp = tid >> 5;
    int wm = warp & 3, wn = warp >> 2;
    int m0 = blockIdx.y * 128;
    int n0 = blockIdx.x * 128;                    // fp8 col base
    int r = lane >> 2, c = lane & 3;
    int q = lane >> 3, rr = lane & 7;             // ldmatrix decomposition

    // staging assignments (256 threads: 128 rows x 16 u32, 2 cp16 each)
    int s_ar = tid >> 1, s_ah = (tid & 1) * 8;
    const uint32_t* a_src = A + (size_t)(m0 + s_ar) * 128 + s_ah;
    const uint32_t* b_src = Wt + (size_t)(n0 + s_ar) * 128 + s_ah;

    // hoisted LDSM base addresses (stage 0, ks 0); step: st*40960B, ks*32B
    uint32_t aAddr[2], bAddr[4];
#pragma unroll
    for (int mt = 0; mt < 2; mt++)
        aAddr[mt] = (uint32_t)__cvta_generic_to_shared(
            &sm.s.A[0][wm * 32 + mt * 16 + rr + (q & 1) * 8][(q >> 1) * 4]);
#pragma unroll
    for (int p = 0; p < 4; p++)
        bAddr[p] = (uint32_t)__cvta_generic_to_shared(
            &sm.s.B[0][wn * 64 + p * 16 + (q >> 1) * 8 + rr][(q & 1) * 4]);

    float acc[2][8][4];
#pragma unroll
    for (int mt = 0; mt < 2; mt++)
#pragma unroll
        for (int nt = 0; nt < 8; nt++)
#pragma unroll
            for (int z = 0; z < 4; z++) acc[mt][nt][z] = 0.0f;

#define PREFETCH(st, t)                                                         \
    do {                                                                        \
        const uint32_t* ap = a_src + (t) * 16;                                  \
        uint32_t da = (uint32_t)__cvta_generic_to_shared(&sm.s.A[st][s_ar][s_ah]); \
        cp16(da, ap); cp16(da + 16, ap + 4);                                    \
        const uint32_t* bp = b_src + (t) * 16;                                  \
        uint32_t db = (uint32_t)__cvta_generic_to_shared(&sm.s.B[st][s_ar][s_ah]); \
        cp16(db, bp); cp16(db + 16, bp + 4);                                    \
        asm volatile("cp.async.commit_group;");                                 \
    } while (0)

    PREFETCH(0, 0);

    const int T = 8;   // 512 / 64
    for (int t = 0; t < T; t++) {
        int st = t & 1;
        uint32_t stOff = st * (STAGE_U32 * 4);
        asm volatile("cp.async.wait_group 0;");
        __syncthreads();   // data for tile t visible; all warps done with t-1
        if (t + 1 < T)
            PREFETCH(st ^ 1, t + 1);

#pragma unroll
        for (int ks = 0; ks < 2; ks++) {
            uint32_t kOff = stOff + ks * 32;
            uint32_t af[2][4];
#pragma unroll
            for (int mt = 0; mt < 2; mt++)
                ldsm_x4(af[mt][0], af[mt][1], af[mt][2], af[mt][3], aAddr[mt] + kOff);
#pragma unroll
            for (int p = 0; p < 4; p++) {
                uint32_t b0, b1, b2, b3;
                ldsm_x4(b0, b1, b2, b3, bAddr[p] + kOff);
#pragma unroll
                for (int mt = 0; mt < 2; mt++) {
                    mma_e4m3(acc[mt][2 * p][0], acc[mt][2 * p][1],
                             acc[mt][2 * p][2], acc[mt][2 * p][3],
                             af[mt][0], af[mt][1], af[mt][2], af[mt][3], b0, b1);
                    mma_e4m3(acc[mt][2 * p + 1][0], acc[mt][2 * p + 1][1],
                             acc[mt][2 * p + 1][2], acc[mt][2 * p + 1][3],
                             af[mt][0], af[mt][1], af[mt][2], af[mt][3], b2, b3);
                }
            }
        }
    }
#undef PREFETCH

    __syncthreads();   // all reads of sm.s done before epilogue aliases it

    // epilogue: fragments -> smem u16 (2 fp8 each) -> coalesced u32 out
#pragma unroll
    for (int mt = 0; mt < 2; mt++) {
#pragma unroll
        for (int nt = 0; nt < 8; nt++) {
            int lr = wm * 32 + mt * 16 + r;       // local row
            int uc = wn * 32 + nt * 4 + c;        // u16 col (2 fp8)
            unsigned short p0, p1;
            asm("cvt.rn.satfinite.e4m3x2.f32 %0, %1, %2;"
                : "=h"(p0) : "f"(acc[mt][nt][1]), "f"(acc[mt][nt][0]));
            asm("cvt.rn.satfinite.e4m3x2.f32 %0, %1, %2;"
                : "=h"(p1) : "f"(acc[mt][nt][3]), "f"(acc[mt][nt][2]));
            sm.e[lr][uc] = p0;
            sm.e[lr + 8][uc] = p1;
        }
    }
    __syncthreads();

    // copy out: 128 rows x 32 u32; 2 threads per row, 16 u32 (4 uint4) each
    {
        int row = tid >> 1, part = tid & 1;
        int grow = m0 + row;
        if (grow < NN) {
            const uint4* src = (const uint4*)((const uint32_t*)&sm.e[row][0] + part * 16);
            uint4* dst = (uint4*)(g_xwb + (size_t)grow * cStride + (n0 >> 2) + part * 16);
#pragma unroll
            for (int z = 0; z < 4; z++) dst[z] = src[z];
        }
    }
}

// ---------------------------------------------------------------------------
// agg (512-wide): one block (128 thr) per dst. fp8 -> half2 HFMA2 -> fp8.
// (R13-proven 2x-unrolled form.)
// ---------------------------------------------------------------------------
__global__ __launch_bounds__(128) void agg_fp8(const float* __restrict__ b, int oSel)
{
    uint32_t* o = oSel ? g_act1 : g_act0;
    const uint32_t* X = g_xwb;   // row stride 128 u32
    int i = blockIdx.x, j = threadIdx.x;

    int p0 = g_off[i], p1 = g_off[i + 1];
    float s = g_dis[i];
    __half2 s2 = __float2half2_rn(s * s);

    float4 bb = ((const float4*)b)[j];
    __half2 acc0 = __floats2half2_rn(bb.x, bb.y);
    __half2 acc1 = __floats2half2_rn(bb.z, bb.w);
    {
        __half2 v0, v1;
        unpk_h2(X[(size_t)i * 128 + j], v0, v1);
        acc0 = __hfma2(s2, v0, acc0);
        acc1 = __hfma2(s2, v1, acc1);
    }

    int p = p0;
    for (; p + 1 < p1; p += 2) {
        int sA = g_srcA[p], sB = g_srcA[p + 1];
        __half2 eA = u32h2(g_enA[p]);
        __half2 eB = u32h2(g_enA[p + 1]);
        uint32_t wA = X[(size_t)sA * 128 + j];
        uint32_t wB = X[(size_t)sB * 128 + j];
        __half2 a0, a1, d0, d1;
        unpk_h2(wA, a0, a1);
        unpk_h2(wB, d0, d1);
        acc0 = __hfma2(eA, a0, acc0);
        acc1 = __hfma2(eA, a1, acc1);
        acc0 = __hfma2(eB, d0, acc0);
        acc1 = __hfma2(eB, d1, acc1);
    }
    if (p < p1) {
        int sA = g_srcA[p];
        __half2 eA = u32h2(g_enA[p]);
        __half2 a0, a1;
        unpk_h2(X[(size_t)sA * 128 + j], a0, a1);
        acc0 = __hfma2(eA, a0, acc0);
        acc1 = __hfma2(eA, a1, acc1);
    }
    o[(size_t)i * 128 + j] = pkh2(lk2(acc0), lk2(acc1));
}

// ---------------------------------------------------------------------------
// layer-4 agg fused with mean-pool: 64 thr/block, 16 dst rows per block.
// ---------------------------------------------------------------------------
__global__ __launch_bounds__(64) void agg_pool(const float* __restrict__ b)
{
    const uint32_t* X = g_xwb;   // row stride 64 u32
    int j = threadIdx.x;
    int i0 = blockIdx.x * 16;
    int i1 = i0 + 16; if (i1 > NN) i1 = NN;
    float4 bb = ((const float4*)b)[j];
    __half2 bh0 = __floats2half2_rn(bb.x, bb.y);
    __half2 bh1 = __floats2half2_rn(bb.z, bb.w);
    float4 pool = make_float4(0.f, 0.f, 0.f, 0.f);

    for (int i = i0; i < i1; i++) {
        int p0 = g_off[i], p1 = g_off[i + 1];
        float s = g_dis[i];
        __half2 s2 = __float2half2_rn(s * s);
        __half2 acc0 = bh0, acc1 = bh1;
        {
            __half2 v0, v1;
            unpk_h2(X[(size_t)i * 64 + j], v0, v1);
            acc0 = __hfma2(s2, v0, acc0);
            acc1 = __hfma2(s2, v1, acc1);
        }
        int p = p0;
        for (; p + 1 < p1; p += 2) {
            int sA = g_srcA[p], sB = g_srcA[p + 1];
            __half2 eA = u32h2(g_enA[p]);
            __half2 eB = u32h2(g_enA[p + 1]);
            uint32_t wA = X[(size_t)sA * 64 + j];
            uint32_t wB = X[(size_t)sB * 64 + j];
            __half2 a0, a1, d0, d1;
            unpk_h2(wA, a0, a1);
            unpk_h2(wB, d0, d1);
            acc0 = __hfma2(eA, a0, acc0);
            acc1 = __hfma2(eA, a1, acc1);
            acc0 = __hfma2(eB, d0, acc0);
            acc1 = __hfma2(eB, d1, acc1);
        }
        if (p < p1) {
            int sA = g_srcA[p];
            __half2 eA = u32h2(g_enA[p]);
            __half2 a0, a1;
            unpk_h2(X[(size_t)sA * 64 + j], a0, a1);
            acc0 = __hfma2(eA, a0, acc0);
            acc1 = __hfma2(eA, a1, acc1);
        }
        float2 f0 = __half22float2(lk2(acc0));
        float2 f1 = __half22float2(lk2(acc1));
        pool.x += f0.x; pool.y += f0.y;
        pool.z += f1.x; pool.w += f1.y;
    }
    atomicAdd(&g_pool[j * 4 + 0], pool.x);
    atomicAdd(&g_pool[j * 4 + 1], pool.y);
    atomicAdd(&g_pool[j * 4 + 2], pool.z);
    atomicAdd(&g_pool[j * 4 + 3], pool.w);
}

// ---------------------------------------------------------------------------
// head: mean -> FC(256,64)+leaky -> FC(64,1) -> sigmoid
// ---------------------------------------------------------------------------
__global__ void head_kernel(const float* __restrict__ fcW1,
                            const float* __restrict__ fcb1,
                            const float* __restrict__ fcW2,
                            const float* __restrict__ fcb2,
                            float* __restrict__ out)
{
    __shared__ float g[FO];
    __shared__ float h1[64];
    int t = threadIdx.x;  // 256 threads
    g[t] = g_pool[t] * (1.0f / (float)NN);
    __syncthreads();
    if (t < 64) {
        float acc = fcb1[t];
        for (int c = 0; c < FO; c++)
            acc = fmaf(g[c], fcW1[c * 64 + t], acc);
        h1[t] = leaky(acc);
    }
    __syncthreads();
    if (t == 0) {
        float z = fcb2[0];
        for (int j = 0; j < 64; j++)
            z = fmaf(h1[j], fcW2[j], z);
        out[0] = 1.0f / (1.0f + expf(-z));
    }
}

// ---------------------------------------------------------------------------
// launch — default stream: conv + gemm L1 (ncu slot #4) + layers.
// side stream s1: CSR build chain, forked at entry, joined before agg L1.
// ---------------------------------------------------------------------------
extern "C" void kernel_launch(void* const* d_in, const int* in_sizes, int n_in,
                              void* d_out, int out_size)
{
    const float* x  = (const float*)d_in[0];
    const int*   ei = (const int*)d_in[1];   // int32 or int64 (auto-detected)
    const float* W1 = (const float*)d_in[2];
    const float* b1 = (const float*)d_in[3];
    const float* W2 = (const float*)d_in[4];
    const float* b2 = (const float*)d_in[5];
    const float* W3 = (const float*)d_in[6];
    const float* b3 = (const float*)d_in[7];
    const float* W4 = (const float*)d_in[8];
    const float* b4 = (const float*)d_in[9];
    const float* fcW1 = (const float*)d_in[10];
    const float* fcb1 = (const float*)d_in[11];
    const float* fcW2 = (const float*)d_in[12];
    const float* fcb2 = (const float*)d_in[13];
    float* out = (float*)d_out;

    dim3 g512(4, NP / 128);   // 4 n-tiles of 128 fp8 cols
    dim3 g256(2, NP / 128);   // 2 n-tiles

    const bool haveSide = (g_s1 != 0) && (g_evFork != 0) && (g_evJoin != 0);
    cudaStream_t s1 = haveSide ? g_s1 : (cudaStream_t)0;

    if (haveSide) cudaEventRecord(g_evFork, 0);

    // default stream: L1 prerequisites + L1 GEMM (ncu capture slot = #4)
    convx_kernel<<<(NN * 128 + 255) / 256, 256>>>(x);
    convwT_kernel<<<256, 256>>>(W1, 512, 0);
    convwT_kernel<<<256, 256>>>(W2, 512, 65536);
    gemm_fp8<<<g512, 256>>>(0, 0, 128);
    convwT_kernel<<<256, 256>>>(W3, 512, 131072);
    convwT_kernel<<<128, 256>>>(W4, 256, 196608);

    // side stream: CSR + norm build (independent of the conv/gemm chain)
    if (haveSide) cudaStreamWaitEvent(s1, g_evFork, 0);
    detect_kernel<<<1, 256, 0, s1>>>(ei);
    zero_kernel<<<(NN + 255) / 256, 256, 0, s1>>>();
    count_kernel<<<(EE + 255) / 256, 256, 0, s1>>>(ei);
    scanA_kernel<<<NB, 256, 0, s1>>>();           // also computes dis
    scanB_kernel<<<1, 512, 0, s1>>>();
    scanC_kernel<<<NB, 256, 0, s1>>>();
    fill_kernel<<<(EE + 255) / 256, 256, 0, s1>>>(ei);
    if (haveSide) {
        cudaEventRecord(g_evJoin, s1);
        cudaStreamWaitEvent(0, g_evJoin, 0);      // join before first agg
    }

    // L1 agg
    agg_fp8<<<NN, 128>>>(b1, 1);
    // L2
    gemm_fp8<<<g512, 256>>>(1, 65536, 128);
    agg_fp8<<<NN, 128>>>(b2, 0);
    // L3
    gemm_fp8<<<g512, 256>>>(0, 131072, 128);
    agg_fp8<<<NN, 128>>>(b3, 1);
    // L4 (256 cols, stride 64 u32) + fused pool
    gemm_fp8<<<g256, 256>>>(1, 196608, 64);
    agg_pool<<<(NN + 15) / 16, 64>>>(b4);

    head_kernel<<<1, 256>>>(fcW1, fcb1, fcW2, fcb2, out);
}

// round 16
// speedup vs baseline: 1.4318x; 1.4318x over previous
#include <cuda_runtime.h>
#include <cuda_bf16.h>
#include <cuda_fp16.h>
#include <math.h>
#include <stdint.h>

// ---------------------------------------------------------------------------
// GCNClassifier: 4x GCNConv(512,512,512,256) + mean-pool + FC(256->64->1)
// R16: R13 restored (single stream, .ca staging, 2x-unroll half2 agg)
//      + dis fused into scanA
//      + ONE experiment: 3-stage .ca GEMM pipeline (dynamic smem, wait 1).
// ---------------------------------------------------------------------------

#define NN 100000
#define NP 100096          // padded to multiple of 128 (GEMM M tiles)
#define EE 1600000
#define FH 512
#define FO 256
#define NB 391             // ceil(NN/256)

#define STAGE_B  20480     // one pipeline stage: A(10240) + B(10240) bytes
#define SMEM_DYN (3 * STAGE_B)

// Scratch (device globals — no runtime allocation allowed)
__device__ uint32_t g_act0[NP * 128];   // e4m3 activations (ping)  [row][128 u32]
__device__ uint32_t g_act1[NP * 128];   // e4m3 activations (pong)
__device__ uint32_t g_xwb[NP * 128];    // e4m3 GEMM output
__device__ uint32_t g_wp[229376];       // e4m3 weights TRANSPOSED [N][K/4 u32]
__device__ int      g_cnt[NN];
__device__ int      g_off[NN + 1];
__device__ int      g_cur[NN];
__device__ int      g_bsum[NB];
__device__ int      g_boff[NB];
__device__ int      g_srcA[EE];
__device__ uint32_t g_enA[EE];          // edge norm as half2 broadcast
__device__ float    g_dis[NN];
__device__ float    g_pool[FO];
__device__ int      g_is64;

__device__ __forceinline__ float leaky(float x) {
    return x >= 0.0f ? x : 0.01f * x;
}

__device__ __forceinline__ __half2 u32h2(uint32_t u) {
    return *reinterpret_cast<__half2*>(&u);
}
__device__ __forceinline__ uint32_t h2u32(__half2 h) {
    return *reinterpret_cast<uint32_t*>(&h);
}

// fp8 u32 (4 e4m3) -> two half2
__device__ __forceinline__ void unpk_h2(uint32_t w, __half2& h0, __half2& h1) {
    uint32_t fa, fb;
    unsigned short lo = (unsigned short)(w & 0xffff);
    unsigned short hi = (unsigned short)(w >> 16);
    asm("cvt.rn.f16x2.e4m3x2 %0, %1;" : "=r"(fa) : "h"(lo));
    asm("cvt.rn.f16x2.e4m3x2 %0, %1;" : "=r"(fb) : "h"(hi));
    h0 = u32h2(fa);
    h1 = u32h2(fb);
}

// two half2 -> fp8 u32
__device__ __forceinline__ uint32_t pkh2(__half2 h0, __half2 h1) {
    unsigned short lo, hi;
    uint32_t u0 = h2u32(h0), u1 = h2u32(h1);
    asm("cvt.rn.satfinite.e4m3x2.f16x2 %0, %1;" : "=h"(lo) : "r"(u0));
    asm("cvt.rn.satfinite.e4m3x2.f16x2 %0, %1;" : "=h"(hi) : "r"(u1));
    return (uint32_t)lo | ((uint32_t)hi << 16);
}

// leaky in half2: max(x, 0.01*x)
__device__ __forceinline__ __half2 lk2(__half2 x) {
    const __half2 c = __floats2half2_rn(0.01f, 0.01f);
    return __hmax2(x, __hmul2(x, c));
}

// pack 4 floats -> 4 e4m3 in a u32 (byte i = col i)
__device__ __forceinline__ uint32_t pk8(float a, float b, float c, float d) {
    unsigned short lo, hi;
    asm("cvt.rn.satfinite.e4m3x2.f32 %0, %1, %2;" : "=h"(lo) : "f"(b), "f"(a));
    asm("cvt.rn.satfinite.e4m3x2.f32 %0, %1, %2;" : "=h"(hi) : "f"(d), "f"(c));
    return (uint32_t)lo | ((uint32_t)hi << 16);
}

__device__ __forceinline__ int edge_word(const int* __restrict__ w, int p, int is64) {
    return is64 ? w[2 * p] : w[p];   // little-endian: low word == value
}

__device__ __forceinline__ void mma_e4m3(float& c0, float& c1, float& c2, float& c3,
                                         uint32_t a0, uint32_t a1, uint32_t a2, uint32_t a3,
                                         uint32_t b0, uint32_t b1) {
    asm volatile(
        "mma.sync.aligned.m16n8k32.row.col.f32.e4m3.e4m3.f32 "
        "{%0,%1,%2,%3}, {%4,%5,%6,%7}, {%8,%9}, {%0,%1,%2,%3};"
        : "+f"(c0), "+f"(c1), "+f"(c2), "+f"(c3)
        : "r"(a0), "r"(a1), "r"(a2), "r"(a3), "r"(b0), "r"(b1));
}

__device__ __forceinline__ void ldsm_x4(uint32_t& r0, uint32_t& r1,
                                        uint32_t& r2, uint32_t& r3, uint32_t addr) {
    asm volatile("ldmatrix.sync.aligned.m8n8.x4.shared.b16 {%0,%1,%2,%3}, [%4];"
                 : "=r"(r0), "=r"(r1), "=r"(r2), "=r"(r3) : "r"(addr));
}

__device__ __forceinline__ void cp16(uint32_t smem, const void* g) {
    asm volatile("cp.async.ca.shared.global [%0], [%1], 16;" :: "r"(smem), "l"(g));
}

// ---------------------------------------------------------------------------
// dtype detection (parallel): int64 values < N have all-zero odd words
// ---------------------------------------------------------------------------
__global__ void detect_kernel(const int* __restrict__ w) {
    __shared__ int bad;
    if (threadIdx.x == 0) bad = 0;
    __syncthreads();
    int v = w[1 + 2 * threadIdx.x];   // odd words 1..511
    if (v != 0) bad = 1;
    __syncthreads();
    if (threadIdx.x == 0) g_is64 = bad ? 0 : 1;
}

// ---------------------------------------------------------------------------
// CSR build
// ---------------------------------------------------------------------------
__global__ void zero_kernel() {
    int i = blockIdx.x * blockDim.x + threadIdx.x;
    if (i < NN) g_cnt[i] = 0;
    if (i < FO) g_pool[i] = 0.0f;
}

__global__ void count_kernel(const int* __restrict__ w) {
    int e = blockIdx.x * blockDim.x + threadIdx.x;
    if (e < EE) {
        int is64 = g_is64;
        int d = edge_word(w, EE + e, is64);
        atomicAdd(&g_cnt[d], 1);
    }
}

// Parallel scan, 3 phases (scanA also computes dis)
__global__ void scanA_kernel() {   // block partial sums + dis
    __shared__ int sh[256];
    int t = threadIdx.x;
    int i = blockIdx.x * 256 + t;
    int v = (i < NN) ? g_cnt[i] : 0;
    if (i < NN) g_dis[i] = rsqrtf((float)v + 1.0f);
    sh[t] = v;
    __syncthreads();
    for (int off = 128; off > 0; off >>= 1) {
        if (t < off) sh[t] += sh[t + off];
        __syncthreads();
    }
    if (t == 0) g_bsum[blockIdx.x] = sh[0];
}

__global__ __launch_bounds__(512) void scanB_kernel() {  // scan of 391 block sums
    __shared__ int sh[512];
    int t = threadIdx.x;
    int v = (t < NB) ? g_bsum[t] : 0;
    sh[t] = v;
    __syncthreads();
    for (int off = 1; off < 512; off <<= 1) {
        int u = (t >= off) ? sh[t - off] : 0;
        __syncthreads();
        sh[t] += u;
        __syncthreads();
    }
    if (t < NB) g_boff[t] = sh[t] - v;   // exclusive
    if (t == 0) g_off[NN] = EE;
}

__global__ void scanC_kernel() {   // block-local exclusive scan + offsets
    __shared__ int sh[256];
    int b = blockIdx.x, t = threadIdx.x;
    int i = b * 256 + t;
    int v = (i < NN) ? g_cnt[i] : 0;
    sh[t] = v;
    __syncthreads();
    for (int off = 1; off < 256; off <<= 1) {
        int u = (t >= off) ? sh[t - off] : 0;
        __syncthreads();
        sh[t] += u;
        __syncthreads();
    }
    if (i < NN) {
        int excl = g_boff[b] + sh[t] - v;
        g_off[i] = excl;
        g_cur[i] = excl;
    }
}

__global__ void fill_kernel(const int* __restrict__ w) {
    int e = blockIdx.x * blockDim.x + threadIdx.x;
    if (e < EE) {
        int is64 = g_is64;
        int s = edge_word(w, e, is64);
        int d = edge_word(w, EE + e, is64);
        int p = atomicAdd(&g_cur[d], 1);
        g_srcA[p] = s;
        g_enA[p] = h2u32(__float2half2_rn(g_dis[s] * g_dis[d]));
    }
}

// ---------------------------------------------------------------------------
// weight pack TRANSPOSED fp8: W[K][N] f32 -> g_wp[off + n*128 + kk]
// ---------------------------------------------------------------------------
__global__ void convwT_kernel(const float* __restrict__ W, int N, int off) {
    int idx = blockIdx.x * blockDim.x + threadIdx.x;
    int tot = N * 128;
    if (idx < tot) {
        int n = idx >> 7, kk = idx & 127;
        int k0 = kk * 4;
        g_wp[off + idx] = pk8(W[(k0 + 0) * N + n], W[(k0 + 1) * N + n],
                              W[(k0 + 2) * N + n], W[(k0 + 3) * N + n]);
    }
}

// x f32 -> act0 fp8
__global__ void convx_kernel(const float* __restrict__ x) {
    int idx = blockIdx.x * blockDim.x + threadIdx.x;  // < NN*128
    if (idx < NN * 128) {
        float4 v = ((const float4*)x)[idx];
        g_act0[idx] = pk8(v.x, v.y, v.z, v.w);
    }
}

// ---------------------------------------------------------------------------
// fp8 tensor-core GEMM: xwb[M, Ntot] = act[M,512] @ Wt^T   (e4m3, f32 accum)
// BM=128, BN=128 (fp8 cols), BK=64 fp8. 256 thr = 8 warps, wt 32x64.
// 3-stage cp.async.CA pipeline in dynamic smem; 2 CTAs/SM; LDSM fragments.
// Layout per stage: A[128][20] u32 then B[128][20] u32 (rows of 80B, as R13).
// ---------------------------------------------------------------------------
__global__ __launch_bounds__(256, 2) void gemm_fp8(int aSel, int wOff, int cStride)
{
    extern __shared__ __align__(16) char dsm[];
    uint32_t smemBase = (uint32_t)__cvta_generic_to_shared(dsm);

    const uint32_t* A = aSel ? g_act1 : g_act0;   // [NP][128 u32]
    const uint32_t* Wt = g_wp + wOff;             // [Ntot][128 u32]
    int tid = threadIdx.x;
    int lane = tid & 31, warp = tid >> 5;
    int wm = warp & 3, wn = warp >> 2;
    int m0 = blockIdx.y * 128;
    int n0 = blockIdx.x * 128;                    // fp8 col base
    int r = lane >> 2, c = lane & 3;
    int q = lane >> 3, rr = lane & 7;             // ldmatrix decomposition

    // staging assignments (256 threads: 128 rows x 16 u32, 2 cp16 each)
    int s_ar = tid >> 1, s_ah = (tid & 1) * 8;
    const uint32_t* a_src = A + (size_t)(m0 + s_ar) * 128 + s_ah;
    const uint32_t* b_src = Wt + (size_t)(n0 + s_ar) * 128 + s_ah;
    uint32_t aStage = smemBase + (s_ar * 20 + s_ah) * 4;    // stage-0 A slot
    uint32_t bStage = aStage + 10240;                        // stage-0 B slot

    // hoisted LDSM base addresses (stage 0, ks 0); step: stage*20480B, ks*32B
    uint32_t aAddr[2], bAddr[4];
#pragma unroll
    for (int mt = 0; mt < 2; mt++)
        aAddr[mt] = smemBase +
            ((wm * 32 + mt * 16 + rr + (q & 1) * 8) * 20 + (q >> 1) * 4) * 4;
#pragma unroll
    for (int p = 0; p < 4; p++)
        bAddr[p] = smemBase + 10240 +
            ((wn * 64 + p * 16 + (q >> 1) * 8 + rr) * 20 + (q & 1) * 4) * 4;

    float acc[2][8][4];
#pragma unroll
    for (int mt = 0; mt < 2; mt++)
#pragma unroll
        for (int nt = 0; nt < 8; nt++)
#pragma unroll
            for (int z = 0; z < 4; z++) acc[mt][nt][z] = 0.0f;

#define PREFETCH(st, t)                                                        \
    do {                                                                       \
        const uint32_t* ap = a_src + (t) * 16;                                 \
        uint32_t da = aStage + (st) * STAGE_B;                                 \
        cp16(da, ap); cp16(da + 16, ap + 4);                                   \
        const uint32_t* bp = b_src + (t) * 16;                                 \
        uint32_t db = bStage + (st) * STAGE_B;                                 \
        cp16(db, bp); cp16(db + 16, bp + 4);                                   \
        asm volatile("cp.async.commit_group;");                                \
    } while (0)

    PREFETCH(0, 0);
    PREFETCH(1, 1);

    const int T = 8;   // 512 / 64
#pragma unroll
    for (int t = 0; t < T; t++) {
        int st = t % 3;                       // compile-time after unroll
        uint32_t stOff = st * STAGE_B;
        if (t < T - 1)
            asm volatile("cp.async.wait_group 1;");   // tile t ready, t+1 in flight
        else
            asm volatile("cp.async.wait_group 0;");
        __syncthreads();   // tile t visible; all warps done with tile t-1
        if (t + 2 < T)
            PREFETCH((t + 2) % 3, t + 2);     // overwrites tile t-1's buffer

#pragma unroll
        for (int ks = 0; ks < 2; ks++) {
            uint32_t kOff = stOff + ks * 32;
            uint32_t af[2][4];
#pragma unroll
            for (int mt = 0; mt < 2; mt++)
                ldsm_x4(af[mt][0], af[mt][1], af[mt][2], af[mt][3], aAddr[mt] + kOff);
#pragma unroll
            for (int p = 0; p < 4; p++) {
                uint32_t b0, b1, b2, b3;
                ldsm_x4(b0, b1, b2, b3, bAddr[p] + kOff);
#pragma unroll
                for (int mt = 0; mt < 2; mt++) {
                    mma_e4m3(acc[mt][2 * p][0], acc[mt][2 * p][1],
                             acc[mt][2 * p][2], acc[mt][2 * p][3],
                             af[mt][0], af[mt][1], af[mt][2], af[mt][3], b0, b1);
                    mma_e4m3(acc[mt][2 * p + 1][0], acc[mt][2 * p + 1][1],
                             acc[mt][2 * p + 1][2], acc[mt][2 * p + 1][3],
                             af[mt][0], af[mt][1], af[mt][2], af[mt][3], b2, b3);
                }
            }
        }
    }
#undef PREFETCH

    __syncthreads();   // all LDSM reads done before epilogue aliases stage 0

    // epilogue: fragments -> smem u16 (2 fp8 each) -> coalesced u32 out
    uint16_t (*e)[72] = (uint16_t(*)[72])dsm;
#pragma unroll
    for (int mt = 0; mt < 2; mt++) {
#pragma unroll
        for (int nt = 0; nt < 8; nt++) {
            int lr = wm * 32 + mt * 16 + r;       // local row
            int uc = wn * 32 + nt * 4 + c;        // u16 col (2 fp8)
            unsigned short p0, p1;
            asm("cvt.rn.satfinite.e4m3x2.f32 %0, %1, %2;"
                : "=h"(p0) : "f"(acc[mt][nt][1]), "f"(acc[mt][nt][0]));
            asm("cvt.rn.satfinite.e4m3x2.f32 %0, %1, %2;"
                : "=h"(p1) : "f"(acc[mt][nt][3]), "f"(acc[mt][nt][2]));
            e[lr][uc] = p0;
            e[lr + 8][uc] = p1;
        }
    }
    __syncthreads();

    // copy out: 128 rows x 32 u32; 2 threads per row, 16 u32 (4 uint4) each
    {
        int row = tid >> 1, part = tid & 1;
        int grow = m0 + row;
        if (grow < NN) {
            const uint4* src = (const uint4*)((const uint32_t*)&e[row][0] + part * 16);
            uint4* dst = (uint4*)(g_xwb + (size_t)grow * cStride + (n0 >> 2) + part * 16);
#pragma unroll
            for (int z = 0; z < 4; z++) dst[z] = src[z];
        }
    }
}

// ---------------------------------------------------------------------------
// agg (512-wide): one block (128 thr) per dst. fp8 -> half2 HFMA2 -> fp8.
// (R13-proven 2x-unrolled form, untouched.)
// ---------------------------------------------------------------------------
__global__ __launch_bounds__(128) void agg_fp8(const float* __restrict__ b, int oSel)
{
    uint32_t* o = oSel ? g_act1 : g_act0;
    const uint32_t* X = g_xwb;   // row stride 128 u32
    int i = blockIdx.x, j = threadIdx.x;

    int p0 = g_off[i], p1 = g_off[i + 1];
    float s = g_dis[i];
    __half2 s2 = __float2half2_rn(s * s);

    float4 bb = ((const float4*)b)[j];
    __half2 acc0 = __floats2half2_rn(bb.x, bb.y);
    __half2 acc1 = __floats2half2_rn(bb.z, bb.w);
    {
        __half2 v0, v1;
        unpk_h2(X[(size_t)i * 128 + j], v0, v1);
        acc0 = __hfma2(s2, v0, acc0);
        acc1 = __hfma2(s2, v1, acc1);
    }

    int p = p0;
    for (; p + 1 < p1; p += 2) {
        int sA = g_srcA[p], sB = g_srcA[p + 1];
        __half2 eA = u32h2(g_enA[p]);
        __half2 eB = u32h2(g_enA[p + 1]);
        uint32_t wA = X[(size_t)sA * 128 + j];
        uint32_t wB = X[(size_t)sB * 128 + j];
        __half2 a0, a1, d0, d1;
        unpk_h2(wA, a0, a1);
        unpk_h2(wB, d0, d1);
        acc0 = __hfma2(eA, a0, acc0);
        acc1 = __hfma2(eA, a1, acc1);
        acc0 = __hfma2(eB, d0, acc0);
        acc1 = __hfma2(eB, d1, acc1);
    }
    if (p < p1) {
        int sA = g_srcA[p];
        __half2 eA = u32h2(g_enA[p]);
        __half2 a0, a1;
        unpk_h2(X[(size_t)sA * 128 + j], a0, a1);
        acc0 = __hfma2(eA, a0, acc0);
        acc1 = __hfma2(eA, a1, acc1);
    }
    o[(size_t)i * 128 + j] = pkh2(lk2(acc0), lk2(acc1));
}

// ---------------------------------------------------------------------------
// layer-4 agg fused with mean-pool: 64 thr/block, 16 dst rows per block.
// ---------------------------------------------------------------------------
__global__ __launch_bounds__(64) void agg_pool(const float* __restrict__ b)
{
    const uint32_t* X = g_xwb;   // row stride 64 u32
    int j = threadIdx.x;
    int i0 = blockIdx.x * 16;
    int i1 = i0 + 16; if (i1 > NN) i1 = NN;
    float4 bb = ((const float4*)b)[j];
    __half2 bh0 = __floats2half2_rn(bb.x, bb.y);
    __half2 bh1 = __floats2half2_rn(bb.z, bb.w);
    float4 pool = make_float4(0.f, 0.f, 0.f, 0.f);

    for (int i = i0; i < i1; i++) {
        int p0 = g_off[i], p1 = g_off[i + 1];
        float s = g_dis[i];
        __half2 s2 = __float2half2_rn(s * s);
        __half2 acc0 = bh0, acc1 = bh1;
        {
            __half2 v0, v1;
            unpk_h2(X[(size_t)i * 64 + j], v0, v1);
            acc0 = __hfma2(s2, v0, acc0);
            acc1 = __hfma2(s2, v1, acc1);
        }
        int p = p0;
        for (; p + 1 < p1; p += 2) {
            int sA = g_srcA[p], sB = g_srcA[p + 1];
            __half2 eA = u32h2(g_enA[p]);
            __half2 eB = u32h2(g_enA[p + 1]);
            uint32_t wA = X[(size_t)sA * 64 + j];
            uint32_t wB = X[(size_t)sB * 64 + j];
            __half2 a0, a1, d0, d1;
            unpk_h2(wA, a0, a1);
            unpk_h2(wB, d0, d1);
            acc0 = __hfma2(eA, a0, acc0);
            acc1 = __hfma2(eA, a1, acc1);
            acc0 = __hfma2(eB, d0, acc0);
            acc1 = __hfma2(eB, d1, acc1);
        }
        if (p < p1) {
            int sA = g_srcA[p];
            __half2 eA = u32h2(g_enA[p]);
            __half2 a0, a1;
            unpk_h2(X[(size_t)sA * 64 + j], a0, a1);
            acc0 = __hfma2(eA, a0, acc0);
            acc1 = __hfma2(eA, a1, acc1);
        }
        float2 f0 = __half22float2(lk2(acc0));
        float2 f1 = __half22float2(lk2(acc1));
        pool.x += f0.x; pool.y += f0.y;
        pool.z += f1.x; pool.w += f1.y;
    }
    atomicAdd(&g_pool[j * 4 + 0], pool.x);
    atomicAdd(&g_pool[j * 4 + 1], pool.y);
    atomicAdd(&g_pool[j * 4 + 2], pool.z);
    atomicAdd(&g_pool[j * 4 + 3], pool.w);
}

// ---------------------------------------------------------------------------
// head: mean -> FC(256,64)+leaky -> FC(64,1) -> sigmoid
// ---------------------------------------------------------------------------
__global__ void head_kernel(const float* __restrict__ fcW1,
                            const float* __restrict__ fcb1,
                            const float* __restrict__ fcW2,
                            const float* __restrict__ fcb2,
                            float* __restrict__ out)
{
    __shared__ float g[FO];
    __shared__ float h1[64];
    int t = threadIdx.x;  // 256 threads
    g[t] = g_pool[t] * (1.0f / (float)NN);
    __syncthreads();
    if (t < 64) {
        float acc = fcb1[t];
        for (int c = 0; c < FO; c++)
            acc = fmaf(g[c], fcW1[c * 64 + t], acc);
        h1[t] = leaky(acc);
    }
    __syncthreads();
    if (t == 0) {
        float z = fcb2[0];
        for (int j = 0; j < 64; j++)
            z = fmaf(h1[j], fcW2[j], z);
        out[0] = 1.0f / (1.0f + expf(-z));
    }
}

// ---------------------------------------------------------------------------
// launch — single stream (R13 structure); gemm L1 stays in the ncu slot.
// ---------------------------------------------------------------------------
extern "C" void kernel_launch(void* const* d_in, const int* in_sizes, int n_in,
                              void* d_out, int out_size)
{
    const float* x  = (const float*)d_in[0];
    const int*   ei = (const int*)d_in[1];   // int32 or int64 (auto-detected)
    const float* W1 = (const float*)d_in[2];
    const float* b1 = (const float*)d_in[3];
    const float* W2 = (const float*)d_in[4];
    const float* b2 = (const float*)d_in[5];
    const float* W3 = (const float*)d_in[6];
    const float* b3 = (const float*)d_in[7];
    const float* W4 = (const float*)d_in[8];
    const float* b4 = (const float*)d_in[9];
    const float* fcW1 = (const float*)d_in[10];
    const float* fcb1 = (const float*)d_in[11];
    const float* fcW2 = (const float*)d_in[12];
    const float* fcb2 = (const float*)d_in[13];
    float* out = (float*)d_out;

    cudaFuncSetAttribute(gemm_fp8, cudaFuncAttributeMaxDynamicSharedMemorySize, SMEM_DYN);

    dim3 g512(4, NP / 128);   // 4 n-tiles of 128 fp8 cols
    dim3 g256(2, NP / 128);   // 2 n-tiles

    // #1-#3: L1 prerequisites
    convx_kernel<<<(NN * 128 + 255) / 256, 256>>>(x);
    convwT_kernel<<<256, 256>>>(W1, 512, 0);
    convwT_kernel<<<256, 256>>>(W2, 512, 65536);
    // #4: L1 GEMM  (ncu capture slot)
    gemm_fp8<<<g512, 256, SMEM_DYN>>>(0, 0, 128);

    // remaining conversions
    convwT_kernel<<<256, 256>>>(W3, 512, 131072);
    convwT_kernel<<<128, 256>>>(W4, 256, 196608);

    // CSR + norm build (single stream, in order)
    detect_kernel<<<1, 256>>>(ei);
    zero_kernel<<<(NN + 255) / 256, 256>>>();
    count_kernel<<<(EE + 255) / 256, 256>>>(ei);
    scanA_kernel<<<NB, 256>>>();           // also computes dis
    scanB_kernel<<<1, 512>>>();
    scanC_kernel<<<NB, 256>>>();
    fill_kernel<<<(EE + 255) / 256, 256>>>(ei);

    // L1 agg
    agg_fp8<<<NN, 128>>>(b1, 1);
    // L2
    gemm_fp8<<<g512, 256, SMEM_DYN>>>(1, 65536, 128);
    agg_fp8<<<NN, 128>>>(b2, 0);
    // L3
    gemm_fp8<<<g512, 256, SMEM_DYN>>>(0, 131072, 128);
    agg_fp8<<<NN, 128>>>(b3, 1);
    // L4 (256 cols, stride 64 u32) + fused pool
    gemm_fp8<<<g256, 256, SMEM_DYN>>>(1, 196608, 64);
    agg_pool<<<(NN + 15) / 16, 64>>>(b4);

    head_kernel<<<1, 256>>>(fcW1, fcb1, fcW2, fcb2, out);
}